// round 1
// baseline (speedup 1.0000x reference)
#include <cuda_runtime.h>

#define NPTS   4096
#define EMB    768
#define QKVW   2304
#define KCL    64
#define THRESH 1e-4f
#define DKMEPS 1e-6f
#define LNEPS  1e-5f

// ---------------- scratch (static device globals; no allocation) ----------------
__device__ float g_bufA[NPTS * EMB];        // H, later O2
__device__ float g_QKV [NPTS * QKVW];
__device__ float g_bufB[NPTS * EMB];        // O_heads, later Y
__device__ float g_X   [NPTS * EMB];        // transformed embeddings
__device__ float g_xsq [NPTS];
__device__ float g_csq [KCL];
__device__ float g_Cnew[KCL * EMB];
__device__ float g_Cpart[32 * KCL * EMB];   // split-K partials for a^T X
__device__ float g_asum_part[128 * KCL];    // per-block partials of sum_n a[n,k]
__device__ float g_diff_part[48];
__device__ int   g_done;

// ---------------- helpers ----------------
template<int NW>
__device__ __forceinline__ float blockSum(float v, float* red) {
    #pragma unroll
    for (int o = 16; o; o >>= 1) v += __shfl_xor_sync(0xffffffffu, v, o);
    int t = threadIdx.x;
    if ((t & 31) == 0) red[t >> 5] = v;
    __syncthreads();
    float s = 0.f;
    #pragma unroll
    for (int w = 0; w < NW; w++) s += red[w];
    __syncthreads();
    return s;
}

// ---------------- generic SGEMM: OUT[M,N] = act(A[M,K] @ W[N,K]^T + bias) ----------------
template<bool RELU>
__global__ void __launch_bounds__(256) sgemm_nt(
    const float* __restrict__ A, const float* __restrict__ W,
    const float* __restrict__ bias, float* __restrict__ OUT,
    int M, int Nn, int Kd)
{
    __shared__ float sA[16][68];
    __shared__ float sB[16][68];
    const int t  = threadIdx.x;
    const int ty = t >> 4, tx = t & 15;
    const int row0 = blockIdx.y * 64, col0 = blockIdx.x * 64;
    const int lr = t >> 2;
    const int lk = (t & 3) << 2;
    float acc[4][4] = {};
    const float* Ap = A + (size_t)(row0 + lr) * Kd + lk;
    const float* Wp = W + (size_t)(col0 + lr) * Kd + lk;
    for (int k0 = 0; k0 < Kd; k0 += 16) {
        float4 av = *(const float4*)(Ap + k0);
        float4 bv = *(const float4*)(Wp + k0);
        sA[lk+0][lr] = av.x; sA[lk+1][lr] = av.y; sA[lk+2][lr] = av.z; sA[lk+3][lr] = av.w;
        sB[lk+0][lr] = bv.x; sB[lk+1][lr] = bv.y; sB[lk+2][lr] = bv.z; sB[lk+3][lr] = bv.w;
        __syncthreads();
        #pragma unroll
        for (int kk = 0; kk < 16; kk++) {
            float4 a4 = *(const float4*)&sA[kk][ty << 2];
            float4 b4 = *(const float4*)&sB[kk][tx << 2];
            float ar[4] = {a4.x, a4.y, a4.z, a4.w};
            float br[4] = {b4.x, b4.y, b4.z, b4.w};
            #pragma unroll
            for (int i = 0; i < 4; i++)
                #pragma unroll
                for (int j = 0; j < 4; j++)
                    acc[i][j] = fmaf(ar[i], br[j], acc[i][j]);
        }
        __syncthreads();
    }
    #pragma unroll
    for (int i = 0; i < 4; i++) {
        float4 ov;
        float* r = &ov.x;
        #pragma unroll
        for (int j = 0; j < 4; j++) {
            float v = acc[i][j] + bias[col0 + (tx << 2) + j];
            if (RELU) v = fmaxf(v, 0.f);
            r[j] = v;
        }
        *(float4*)&OUT[(size_t)(row0 + (ty << 2) + i) * Nn + col0 + (tx << 2)] = ov;
    }
}

// ---------------- flash attention: 12 heads, hd=64, N=4096 ----------------
// grid (64 qblocks, 12 heads), 256 threads, dyn smem 3*64*68*4 = 52224 B
__global__ void __launch_bounds__(256) flash_attn(
    const float* __restrict__ QKV, float* __restrict__ O)
{
    extern __shared__ float sm[];
    float* sQ = sm;               // [64][68] transposed [d][r]
    float* sK = sm + 64 * 68;     // transposed [d][c]; reused as V natural [c][d]
    float* sP = sm + 2 * 64 * 68; // [c][q], stride 68
    const int t  = threadIdx.x;
    const int ty = t >> 4, tx = t & 15;
    const int qb = blockIdx.x, h = blockIdx.y;
    const int d4 = tx << 2;

    #pragma unroll
    for (int p = 0; p < 4; p++) {
        int r = ty + p * 16;
        float4 q = *(const float4*)&QKV[(size_t)(qb * 64 + r) * QKVW + h * 64 + d4];
        sQ[(d4+0)*68 + r] = q.x; sQ[(d4+1)*68 + r] = q.y;
        sQ[(d4+2)*68 + r] = q.z; sQ[(d4+3)*68 + r] = q.w;
    }
    float o[4][4] = {};
    float m[4], l[4];
    #pragma unroll
    for (int i = 0; i < 4; i++) { m[i] = -1e30f; l[i] = 0.f; }
    __syncthreads();

    for (int kb = 0; kb < 64; kb++) {
        #pragma unroll
        for (int p = 0; p < 4; p++) {
            int c = ty + p * 16;
            float4 kv = *(const float4*)&QKV[(size_t)(kb * 64 + c) * QKVW + 768 + h * 64 + d4];
            sK[(d4+0)*68 + c] = kv.x; sK[(d4+1)*68 + c] = kv.y;
            sK[(d4+2)*68 + c] = kv.z; sK[(d4+3)*68 + c] = kv.w;
        }
        __syncthreads();
        float s[4][4] = {};
        #pragma unroll
        for (int d = 0; d < 64; d++) {
            float4 a4 = *(const float4*)&sQ[d*68 + (ty << 2)];
            float4 b4 = *(const float4*)&sK[d*68 + (tx << 2)];
            float ar[4] = {a4.x, a4.y, a4.z, a4.w};
            float br[4] = {b4.x, b4.y, b4.z, b4.w};
            #pragma unroll
            for (int i = 0; i < 4; i++)
                #pragma unroll
                for (int j = 0; j < 4; j++)
                    s[i][j] = fmaf(ar[i], br[j], s[i][j]);
        }
        float p[4][4];
        #pragma unroll
        for (int i = 0; i < 4; i++) {
            float mx = -1e30f;
            #pragma unroll
            for (int j = 0; j < 4; j++) { s[i][j] *= 0.125f; mx = fmaxf(mx, s[i][j]); }
            #pragma unroll
            for (int off = 8; off; off >>= 1)
                mx = fmaxf(mx, __shfl_xor_sync(0xffffffffu, mx, off));
            float mn = fmaxf(m[i], mx);
            float sc = expf(m[i] - mn);
            float ps = 0.f;
            #pragma unroll
            for (int j = 0; j < 4; j++) { p[i][j] = expf(s[i][j] - mn); ps += p[i][j]; }
            #pragma unroll
            for (int off = 8; off; off >>= 1)
                ps += __shfl_xor_sync(0xffffffffu, ps, off);
            l[i] = l[i] * sc + ps;
            m[i] = mn;
            #pragma unroll
            for (int j = 0; j < 4; j++) o[i][j] *= sc;
        }
        __syncthreads();   // done reading sK as K
        #pragma unroll
        for (int i = 0; i < 4; i++)
            #pragma unroll
            for (int j = 0; j < 4; j++)
                sP[((tx << 2) + j) * 68 + (ty << 2) + i] = p[i][j];
        #pragma unroll
        for (int pp = 0; pp < 4; pp++) {
            int c = ty + pp * 16;
            float4 vv = *(const float4*)&QKV[(size_t)(kb * 64 + c) * QKVW + 1536 + h * 64 + d4];
            *(float4*)&sK[c*68 + d4] = vv;   // V natural [c][d]
        }
        __syncthreads();
        #pragma unroll
        for (int c = 0; c < 64; c++) {
            float4 p4 = *(const float4*)&sP[c*68 + (ty << 2)];
            float4 v4 = *(const float4*)&sK[c*68 + (tx << 2)];
            float pa[4] = {p4.x, p4.y, p4.z, p4.w};
            float vb[4] = {v4.x, v4.y, v4.z, v4.w};
            #pragma unroll
            for (int i = 0; i < 4; i++)
                #pragma unroll
                for (int j = 0; j < 4; j++)
                    o[i][j] = fmaf(pa[i], vb[j], o[i][j]);
        }
        __syncthreads();   // protect sK/sP before next kb
    }
    #pragma unroll
    for (int i = 0; i < 4; i++) {
        float inv = 1.f / l[i];
        float4 ov;
        ov.x = o[i][0]*inv; ov.y = o[i][1]*inv; ov.z = o[i][2]*inv; ov.w = o[i][3]*inv;
        *(float4*)&O[(size_t)(qb * 64 + (ty << 2) + i) * EMB + h * 64 + (tx << 2)] = ov;
    }
}

// ---------------- residual + layernorm + xsq ----------------
__global__ void __launch_bounds__(256) ln_kernel(
    const float* __restrict__ x0, const float* __restrict__ y,
    const float* __restrict__ lg, const float* __restrict__ lb)
{
    __shared__ float red[8];
    int r = blockIdx.x, t = threadIdx.x;
    float z[3];
    float s = 0.f;
    #pragma unroll
    for (int i = 0; i < 3; i++) {
        int c = t + i * 256;
        z[i] = 0.5f * x0[(size_t)r * EMB + c] + 0.5f * y[(size_t)r * EMB + c];
        s += z[i];
    }
    s = blockSum<8>(s, red);
    float mu = s * (1.f / 768.f);
    float v = 0.f;
    #pragma unroll
    for (int i = 0; i < 3; i++) { float dz = z[i] - mu; v = fmaf(dz, dz, v); }
    v = blockSum<8>(v, red);
    float rstd = rsqrtf(v * (1.f / 768.f) + LNEPS);
    float q = 0.f;
    #pragma unroll
    for (int i = 0; i < 3; i++) {
        int c = t + i * 256;
        float xv = (z[i] - mu) * rstd * lg[c] + lb[c];
        g_X[(size_t)r * EMB + c] = xv;
        q = fmaf(xv, xv, q);
    }
    q = blockSum<8>(q, red);
    if (t == 0) g_xsq[r] = q;
}

// ---------------- DKM: C0 = X[init_idx]; also csq; reset done ----------------
__global__ void __launch_bounds__(768) gather_init(
    const int* __restrict__ idx, float* __restrict__ C_out)
{
    __shared__ float red[24];
    int k = blockIdx.x, t = threadIdx.x;
    if (k == 0 && t == 0) g_done = 0;
    int srow = idx[k];
    float v = g_X[(size_t)srow * EMB + t];
    C_out[k * EMB + t] = v;
    float s = blockSum<24>(v * v, red);
    if (t == 0) g_csq[k] = s;
}

// ---------------- DKM: advance (diff check -> freeze, C <- Cnew, csq) ----------------
__global__ void __launch_bounds__(768) advance_k(float* __restrict__ C_out)
{
    if (g_done) return;
    float diff = 0.f;
    #pragma unroll
    for (int p = 0; p < 48; p++) diff += g_diff_part[p];
    if (diff <= THRESH) {
        if (blockIdx.x == 0 && threadIdx.x == 0) g_done = 1;
        return;
    }
    __shared__ float red[24];
    int k = blockIdx.x, t = threadIdx.x;
    float v = g_Cnew[k * EMB + t];
    C_out[k * EMB + t] = v;
    float s = blockSum<24>(v * v, red);
    if (t == 0) g_csq[k] = s;
}

// ---------------- DKM: assignments a = softmax(-2*cdist(X,C)) (fused GEMM+softmax) ----
// grid 128 blocks (32 rows each), 256 threads (16x16; each thread 2 rows x 4 cols)
__global__ void __launch_bounds__(256) assign_k(
    const float* __restrict__ C, float* __restrict__ a_out)
{
    if (g_done) return;
    __shared__ float sX[16][36];
    __shared__ float sC[16][68];
    __shared__ float s_part[64][17];
    int t = threadIdx.x;
    int ty = t >> 4, tx = t & 15;
    int row0 = blockIdx.x * 32;
    float acc[2][4] = {};
    int xr = t >> 3, xk = (t & 7) << 1;
    int cr = t >> 2, ck = (t & 3) << 2;
    for (int k0 = 0; k0 < EMB; k0 += 16) {
        float2 xv = *(const float2*)&g_X[(size_t)(row0 + xr) * EMB + k0 + xk];
        sX[xk][xr] = xv.x; sX[xk+1][xr] = xv.y;
        float4 cv = *(const float4*)&C[cr * EMB + k0 + ck];
        sC[ck+0][cr] = cv.x; sC[ck+1][cr] = cv.y; sC[ck+2][cr] = cv.z; sC[ck+3][cr] = cv.w;
        __syncthreads();
        #pragma unroll
        for (int kk = 0; kk < 16; kk++) {
            float2 x2 = *(const float2*)&sX[kk][ty << 1];
            float4 c4 = *(const float4*)&sC[kk][tx << 2];
            float cr4[4] = {c4.x, c4.y, c4.z, c4.w};
            #pragma unroll
            for (int j = 0; j < 4; j++) {
                acc[0][j] = fmaf(x2.x, cr4[j], acc[0][j]);
                acc[1][j] = fmaf(x2.y, cr4[j], acc[1][j]);
            }
        }
        __syncthreads();
    }
    float av[2][4];
    #pragma unroll
    for (int i = 0; i < 2; i++) {
        int row = row0 + (ty << 1) + i;
        float xs = g_xsq[row];
        float lgt[4];
        float mx = -1e30f;
        #pragma unroll
        for (int j = 0; j < 4; j++) {
            float d2 = xs + g_csq[(tx << 2) + j] - 2.f * acc[i][j];
            float dd = sqrtf(fmaxf(d2, 0.f));
            lgt[j] = -2.f * dd;
            mx = fmaxf(mx, lgt[j]);
        }
        #pragma unroll
        for (int off = 8; off; off >>= 1)
            mx = fmaxf(mx, __shfl_xor_sync(0xffffffffu, mx, off));
        float ps = 0.f;
        #pragma unroll
        for (int j = 0; j < 4; j++) { av[i][j] = expf(lgt[j] - mx); ps += av[i][j]; }
        #pragma unroll
        for (int off = 8; off; off >>= 1)
            ps += __shfl_xor_sync(0xffffffffu, ps, off);
        float4 ov;
        ov.x = av[i][0] / ps; ov.y = av[i][1] / ps;
        ov.z = av[i][2] / ps; ov.w = av[i][3] / ps;
        av[i][0] = ov.x; av[i][1] = ov.y; av[i][2] = ov.z; av[i][3] = ov.w;
        *(float4*)&a_out[(size_t)row * KCL + (tx << 2)] = ov;
    }
    // deterministic per-block a_sum partials
    #pragma unroll
    for (int j = 0; j < 4; j++)
        s_part[(tx << 2) + j][ty] = av[0][j] + av[1][j];
    __syncthreads();
    if (t < 64) {
        float s = 0.f;
        #pragma unroll
        for (int w = 0; w < 16; w++) s += s_part[t][w];
        g_asum_part[blockIdx.x * 64 + t] = s;
    }
}

// ---------------- DKM: split-K partials of a^T @ X -> g_Cpart ----------------
// grid (12 e-tiles, 32 n-chunks), 256 threads, each thread 4x4
__global__ void __launch_bounds__(256) update_k(const float* __restrict__ a)
{
    if (g_done) return;
    __shared__ float sa[16][68];
    __shared__ float sx[16][68];
    int t = threadIdx.x, ty = t >> 4, tx = t & 15;
    int eb = blockIdx.x;  // 0..11
    int cb = blockIdx.y;  // 0..31
    int n0 = cb * 128;
    float acc[4][4] = {};
    int nn = t >> 4, c4 = (t & 15) << 2;
    for (int nt = 0; nt < 128; nt += 16) {
        int n = n0 + nt + nn;
        *(float4*)&sa[nn][c4] = *(const float4*)&a[(size_t)n * KCL + c4];
        *(float4*)&sx[nn][c4] = *(const float4*)&g_X[(size_t)n * EMB + eb * 64 + c4];
        __syncthreads();
        #pragma unroll
        for (int q = 0; q < 16; q++) {
            float4 a4 = *(const float4*)&sa[q][ty << 2];
            float4 x4 = *(const float4*)&sx[q][tx << 2];
            float ar[4] = {a4.x, a4.y, a4.z, a4.w};
            float xr4[4] = {x4.x, x4.y, x4.z, x4.w};
            #pragma unroll
            for (int i = 0; i < 4; i++)
                #pragma unroll
                for (int j = 0; j < 4; j++)
                    acc[i][j] = fmaf(ar[i], xr4[j], acc[i][j]);
        }
        __syncthreads();
    }
    #pragma unroll
    for (int i = 0; i < 4; i++)
        #pragma unroll
        for (int j = 0; j < 4; j++)
            g_Cpart[(size_t)(cb * 64 + (ty << 2) + i) * EMB + eb * 64 + (tx << 2) + j] = acc[i][j];
}

// ---------------- DKM: reduce partials -> Cnew = (a^T X)/a_sum; diff partials -------
__global__ void __launch_bounds__(1024) finalize_k(const float* __restrict__ C)
{
    if (g_done) return;
    __shared__ float s_asum[64];
    __shared__ float red[32];
    int t = threadIdx.x;
    if (t < 64) {
        float s = 0.f;
        #pragma unroll 4
        for (int bb = 0; bb < 128; bb++) s += g_asum_part[bb * 64 + t];
        s_asum[t] = s + DKMEPS;
    }
    __syncthreads();
    int i = blockIdx.x * 1024 + t;
    float s = 0.f;
    #pragma unroll
    for (int p = 0; p < 32; p++) s += g_Cpart[(size_t)p * (KCL * EMB) + i];
    float c = s / s_asum[i / EMB];
    g_Cnew[i] = c;
    float d = fabsf(c - C[i]);
    #pragma unroll
    for (int o = 16; o; o >>= 1) d += __shfl_xor_sync(0xffffffffu, d, o);
    if ((t & 31) == 0) red[t >> 5] = d;
    __syncthreads();
    if (t == 0) {
        float tot = 0.f;
        #pragma unroll
        for (int w = 0; w < 32; w++) tot += red[w];
        g_diff_part[blockIdx.x] = tot;
    }
}

// ---------------- host ----------------
extern "C" void kernel_launch(void* const* d_in, const int* in_sizes, int n_in,
                              void* d_out, int out_size)
{
    const float* x0     = (const float*)d_in[0];
    const float* fc1_w  = (const float*)d_in[1];
    const float* fc1_b  = (const float*)d_in[2];
    const float* fc2_w  = (const float*)d_in[3];
    const float* fc2_b  = (const float*)d_in[4];
    const float* inp_w  = (const float*)d_in[5];
    const float* inp_b  = (const float*)d_in[6];
    const float* out_w  = (const float*)d_in[7];
    const float* out_b  = (const float*)d_in[8];
    const float* ln_g   = (const float*)d_in[9];
    const float* ln_b   = (const float*)d_in[10];
    const int*   iidx   = (const int*)d_in[11];

    float* outC = (float*)d_out;              // [64, 768]
    float* outA = (float*)d_out + KCL * EMB;  // [4096, 64]

    void *pA, *pQ, *pB;
    cudaGetSymbolAddress(&pA, g_bufA);
    cudaGetSymbolAddress(&pQ, g_QKV);
    cudaGetSymbolAddress(&pB, g_bufB);
    float* bufA = (float*)pA;
    float* qkv  = (float*)pQ;
    float* bufB = (float*)pB;

    const int FLASH_SMEM = 3 * 64 * 68 * 4;
    cudaFuncSetAttribute(flash_attn, cudaFuncAttributeMaxDynamicSharedMemorySize, FLASH_SMEM);

    // ---- transform ----
    sgemm_nt<true ><<<dim3(EMB/64,  NPTS/64), 256>>>(x0,   fc1_w, fc1_b, bufA, NPTS, EMB,  EMB);
    sgemm_nt<false><<<dim3(QKVW/64, NPTS/64), 256>>>(bufA, inp_w, inp_b, qkv,  NPTS, QKVW, EMB);
    flash_attn<<<dim3(64, 12), 256, FLASH_SMEM>>>(qkv, bufB);
    sgemm_nt<false><<<dim3(EMB/64, NPTS/64), 256>>>(bufB, out_w, out_b, bufA, NPTS, EMB, EMB);
    sgemm_nt<true ><<<dim3(EMB/64, NPTS/64), 256>>>(bufA, fc2_w, fc2_b, bufB, NPTS, EMB, EMB);
    ln_kernel<<<NPTS, 256>>>(x0, bufB, ln_g, ln_b);

    // ---- DKM loop: initial step (it=0) + up to 100 bodies, freeze-flag semantics ----
    gather_init<<<KCL, 768>>>(iidx, outC);
    for (int it = 0; it <= 100; it++) {
        if (it > 0) advance_k<<<KCL, 768>>>(outC);
        assign_k<<<NPTS/32, 256>>>(outC, outA);
        if (it < 100) {
            update_k<<<dim3(12, 32), 256>>>(outA);
            finalize_k<<<48, 1024>>>(outC);
        }
    }
}

// round 2
// speedup vs baseline: 1.0150x; 1.0150x over previous
#include <cuda_runtime.h>

#define NPTS   4096
#define EMB    768
#define QKVW   2304
#define KCL    64
#define THRESH 1e-4f
#define DKMEPS 1e-6f
#define LNEPS  1e-5f

// ---------------- scratch (static device globals; no allocation) ----------------
__device__ float g_bufA[NPTS * EMB];        // H, later O2
__device__ float g_QKV [NPTS * QKVW];
__device__ float g_bufB[NPTS * EMB];        // O_heads, later Y
__device__ float g_X   [NPTS * EMB];        // transformed embeddings
__device__ float g_xsq [NPTS];
__device__ float g_csq [KCL];
__device__ float g_Cnew[KCL * EMB];
__device__ float g_Cpart[32 * KCL * EMB];   // split-K partials for a^T X
__device__ float g_asum_part[128 * KCL];    // per-block partials of sum_n a[n,k]
__device__ float g_diff_part[48];
__device__ int   g_done;

// ---------------- helpers ----------------
template<int NW>
__device__ __forceinline__ float blockSum(float v, float* red) {
    #pragma unroll
    for (int o = 16; o; o >>= 1) v += __shfl_xor_sync(0xffffffffu, v, o);
    int t = threadIdx.x;
    if ((t & 31) == 0) red[t >> 5] = v;
    __syncthreads();
    float s = 0.f;
    #pragma unroll
    for (int w = 0; w < NW; w++) s += red[w];
    __syncthreads();
    return s;
}

// ---------------- SGEMM 128x128: OUT[M,N] = act(A[M,K] @ W[N,K]^T + bias) ----------
// grid (Nn/128, M/128), 256 threads, double-buffered smem, 8x8 per thread
template<bool RELU>
__global__ void __launch_bounds__(256) sgemm128(
    const float* __restrict__ A, const float* __restrict__ W,
    const float* __restrict__ bias, float* __restrict__ OUT,
    int Nn, int Kd)
{
    __shared__ float sA[2][8][132];
    __shared__ float sB[2][8][132];
    const int t  = threadIdx.x;
    const int tx = t & 15, ty = t >> 4;
    const int row0 = blockIdx.y * 128, col0 = blockIdx.x * 128;
    const int lr = t >> 1;          // 0..127
    const int lk = (t & 1) << 2;    // 0 or 4
    const float* Ap = A + (size_t)(row0 + lr) * Kd + lk;
    const float* Wp = W + (size_t)(col0 + lr) * Kd + lk;

    float acc[8][8] = {};

    // preload slab 0
    {
        float4 av = *(const float4*)(Ap);
        float4 bv = *(const float4*)(Wp);
        sA[0][lk+0][lr] = av.x; sA[0][lk+1][lr] = av.y;
        sA[0][lk+2][lr] = av.z; sA[0][lk+3][lr] = av.w;
        sB[0][lk+0][lr] = bv.x; sB[0][lk+1][lr] = bv.y;
        sB[0][lk+2][lr] = bv.z; sB[0][lk+3][lr] = bv.w;
    }
    __syncthreads();

    const int nk = Kd >> 3;
    for (int ks = 0; ks < nk; ks++) {
        const int cur = ks & 1;
        float4 a2, b2;
        const bool more = (ks + 1 < nk);
        if (more) {
            a2 = *(const float4*)(Ap + (ks + 1) * 8);
            b2 = *(const float4*)(Wp + (ks + 1) * 8);
        }
        #pragma unroll
        for (int kk = 0; kk < 8; kk++) {
            float4 a0 = *(const float4*)&sA[cur][kk][ty << 3];
            float4 a1 = *(const float4*)&sA[cur][kk][(ty << 3) + 4];
            float4 b0 = *(const float4*)&sB[cur][kk][tx << 3];
            float4 b1 = *(const float4*)&sB[cur][kk][(tx << 3) + 4];
            float ar[8] = {a0.x,a0.y,a0.z,a0.w,a1.x,a1.y,a1.z,a1.w};
            float br[8] = {b0.x,b0.y,b0.z,b0.w,b1.x,b1.y,b1.z,b1.w};
            #pragma unroll
            for (int i = 0; i < 8; i++)
                #pragma unroll
                for (int j = 0; j < 8; j++)
                    acc[i][j] = fmaf(ar[i], br[j], acc[i][j]);
        }
        if (more) {
            const int nxt = cur ^ 1;
            sA[nxt][lk+0][lr] = a2.x; sA[nxt][lk+1][lr] = a2.y;
            sA[nxt][lk+2][lr] = a2.z; sA[nxt][lk+3][lr] = a2.w;
            sB[nxt][lk+0][lr] = b2.x; sB[nxt][lk+1][lr] = b2.y;
            sB[nxt][lk+2][lr] = b2.z; sB[nxt][lk+3][lr] = b2.w;
            __syncthreads();
        }
    }
    // epilogue
    #pragma unroll
    for (int i = 0; i < 8; i++) {
        #pragma unroll
        for (int jv = 0; jv < 2; jv++) {
            float4 ov;
            float* r = &ov.x;
            #pragma unroll
            for (int j = 0; j < 4; j++) {
                float v = acc[i][jv * 4 + j] + bias[col0 + (tx << 3) + jv * 4 + j];
                if (RELU) v = fmaxf(v, 0.f);
                r[j] = v;
            }
            *(float4*)&OUT[(size_t)(row0 + (ty << 3) + i) * Nn + col0 + (tx << 3) + jv * 4] = ov;
        }
    }
}

// ---------------- flash attention v2: Q-tile 128, K-tile 64, hd=64 ----------------
// grid (32 qblocks, 12 heads), 256 threads, dyn smem 100 KB
#define FL_SMEM ((64*132 + 64*68 + 64*68 + 64*132) * 4)
__global__ void __launch_bounds__(256) flash2(
    const float* __restrict__ QKV, float* __restrict__ O)
{
    extern __shared__ float sm[];
    float* sQ = sm;                          // [d=64][r=128] stride 132
    float* sK = sQ + 64 * 132;               // [d=64][c=64]  stride 68
    float* sV = sK + 64 * 68;                // [c=64][d=64]  stride 68
    float* sP = sV + 64 * 68;                // [c=64][q=128] stride 132
    const int t  = threadIdx.x;
    const int tx = t & 15, ty = t >> 4;
    const int qb = blockIdx.x, h = blockIdx.y;

    // load Q transposed: each thread 8 float4 chunks
    {
        int qr = t & 127;
        int half = t >> 7;            // 0/1
        #pragma unroll
        for (int p = 0; p < 8; p++) {
            int d4 = half * 32 + p * 4;
            float4 q = *(const float4*)&QKV[(size_t)(qb * 128 + qr) * QKVW + h * 64 + d4];
            sQ[(d4+0)*132 + qr] = q.x; sQ[(d4+1)*132 + qr] = q.y;
            sQ[(d4+2)*132 + qr] = q.z; sQ[(d4+3)*132 + qr] = q.w;
        }
    }
    float o[8][4] = {};
    float m[8], l[8];
    #pragma unroll
    for (int i = 0; i < 8; i++) { m[i] = -1e30f; l[i] = 0.f; }

    for (int kb = 0; kb < 64; kb++) {
        // load K (transposed) and V (natural)
        {
            int kr = t & 63;
            int half = t >> 6;        // 0..3
            #pragma unroll
            for (int p = 0; p < 4; p++) {
                int d4 = half * 16 + p * 4;
                float4 kv = *(const float4*)&QKV[(size_t)(kb * 64 + kr) * QKVW + 768 + h * 64 + d4];
                sK[(d4+0)*68 + kr] = kv.x; sK[(d4+1)*68 + kr] = kv.y;
                sK[(d4+2)*68 + kr] = kv.z; sK[(d4+3)*68 + kr] = kv.w;
                float4 vv = *(const float4*)&QKV[(size_t)(kb * 64 + kr) * QKVW + 1536 + h * 64 + d4];
                *(float4*)&sV[kr*68 + d4] = vv;
            }
        }
        __syncthreads();
        float s[8][4] = {};
        #pragma unroll
        for (int d = 0; d < 64; d++) {
            float4 a0 = *(const float4*)&sQ[d*132 + (ty << 3)];
            float4 a1 = *(const float4*)&sQ[d*132 + (ty << 3) + 4];
            float4 b4 = *(const float4*)&sK[d*68 + (tx << 2)];
            float ar[8] = {a0.x,a0.y,a0.z,a0.w,a1.x,a1.y,a1.z,a1.w};
            float br[4] = {b4.x,b4.y,b4.z,b4.w};
            #pragma unroll
            for (int i = 0; i < 8; i++)
                #pragma unroll
                for (int j = 0; j < 4; j++)
                    s[i][j] = fmaf(ar[i], br[j], s[i][j]);
        }
        float p[8][4];
        #pragma unroll
        for (int i = 0; i < 8; i++) {
            float mx = -1e30f;
            #pragma unroll
            for (int j = 0; j < 4; j++) { s[i][j] *= 0.125f; mx = fmaxf(mx, s[i][j]); }
            #pragma unroll
            for (int off = 8; off; off >>= 1)
                mx = fmaxf(mx, __shfl_xor_sync(0xffffffffu, mx, off));
            float mn = fmaxf(m[i], mx);
            float sc = expf(m[i] - mn);
            float ps = 0.f;
            #pragma unroll
            for (int j = 0; j < 4; j++) { p[i][j] = expf(s[i][j] - mn); ps += p[i][j]; }
            #pragma unroll
            for (int off = 8; off; off >>= 1)
                ps += __shfl_xor_sync(0xffffffffu, ps, off);
            l[i] = l[i] * sc + ps;
            m[i] = mn;
            #pragma unroll
            for (int j = 0; j < 4; j++) o[i][j] *= sc;
        }
        // write P transposed [c][q]
        #pragma unroll
        for (int i = 0; i < 8; i++)
            #pragma unroll
            for (int j = 0; j < 4; j++)
                sP[((tx << 2) + j) * 132 + (ty << 3) + i] = p[i][j];
        __syncthreads();
        #pragma unroll
        for (int c = 0; c < 64; c++) {
            float4 p0 = *(const float4*)&sP[c*132 + (ty << 3)];
            float4 p1 = *(const float4*)&sP[c*132 + (ty << 3) + 4];
            float4 v4 = *(const float4*)&sV[c*68 + (tx << 2)];
            float pa[8] = {p0.x,p0.y,p0.z,p0.w,p1.x,p1.y,p1.z,p1.w};
            float vb[4] = {v4.x,v4.y,v4.z,v4.w};
            #pragma unroll
            for (int i = 0; i < 8; i++)
                #pragma unroll
                for (int j = 0; j < 4; j++)
                    o[i][j] = fmaf(pa[i], vb[j], o[i][j]);
        }
        __syncthreads();   // protect sK/sV/sP before next kb
    }
    #pragma unroll
    for (int i = 0; i < 8; i++) {
        float inv = 1.f / l[i];
        float4 ov;
        ov.x = o[i][0]*inv; ov.y = o[i][1]*inv; ov.z = o[i][2]*inv; ov.w = o[i][3]*inv;
        *(float4*)&O[(size_t)(qb * 128 + (ty << 3) + i) * EMB + h * 64 + (tx << 2)] = ov;
    }
}

// ---------------- residual + layernorm + xsq ----------------
__global__ void __launch_bounds__(256) ln_kernel(
    const float* __restrict__ x0, const float* __restrict__ y,
    const float* __restrict__ lg, const float* __restrict__ lb)
{
    __shared__ float red[8];
    int r = blockIdx.x, t = threadIdx.x;
    float z[3];
    float s = 0.f;
    #pragma unroll
    for (int i = 0; i < 3; i++) {
        int c = t + i * 256;
        z[i] = 0.5f * x0[(size_t)r * EMB + c] + 0.5f * y[(size_t)r * EMB + c];
        s += z[i];
    }
    s = blockSum<8>(s, red);
    float mu = s * (1.f / 768.f);
    float v = 0.f;
    #pragma unroll
    for (int i = 0; i < 3; i++) { float dz = z[i] - mu; v = fmaf(dz, dz, v); }
    v = blockSum<8>(v, red);
    float rstd = rsqrtf(v * (1.f / 768.f) + LNEPS);
    float q = 0.f;
    #pragma unroll
    for (int i = 0; i < 3; i++) {
        int c = t + i * 256;
        float xv = (z[i] - mu) * rstd * lg[c] + lb[c];
        g_X[(size_t)r * EMB + c] = xv;
        q = fmaf(xv, xv, q);
    }
    q = blockSum<8>(q, red);
    if (t == 0) g_xsq[r] = q;
}

// ---------------- DKM: C0 = X[init_idx]; also csq; reset done ----------------
__global__ void __launch_bounds__(768) gather_init(
    const int* __restrict__ idx, float* __restrict__ C_out)
{
    __shared__ float red[24];
    int k = blockIdx.x, t = threadIdx.x;
    if (k == 0 && t == 0) g_done = 0;
    int srow = idx[k];
    float v = g_X[(size_t)srow * EMB + t];
    C_out[k * EMB + t] = v;
    float s = blockSum<24>(v * v, red);
    if (t == 0) g_csq[k] = s;
}

// ---------------- DKM: advance (diff check -> freeze, C <- Cnew, csq) ----------------
__global__ void __launch_bounds__(768) advance_k(float* __restrict__ C_out)
{
    if (g_done) return;
    float diff = 0.f;
    #pragma unroll
    for (int p = 0; p < 48; p++) diff += g_diff_part[p];
    if (diff <= THRESH) {
        if (blockIdx.x == 0 && threadIdx.x == 0) g_done = 1;
        return;
    }
    __shared__ float red[24];
    int k = blockIdx.x, t = threadIdx.x;
    float v = g_Cnew[k * EMB + t];
    C_out[k * EMB + t] = v;
    float s = blockSum<24>(v * v, red);
    if (t == 0) g_csq[k] = s;
}

// ---------------- DKM: assignments a = softmax(-2*cdist(X,C)) (fused GEMM+softmax) ----
__global__ void __launch_bounds__(256) assign_k(
    const float* __restrict__ C, float* __restrict__ a_out)
{
    if (g_done) return;
    __shared__ float sX[16][36];
    __shared__ float sC[16][68];
    __shared__ float s_part[64][17];
    int t = threadIdx.x;
    int ty = t >> 4, tx = t & 15;
    int row0 = blockIdx.x * 32;
    float acc[2][4] = {};
    int xr = t >> 3, xk = (t & 7) << 1;
    int cr = t >> 2, ck = (t & 3) << 2;
    for (int k0 = 0; k0 < EMB; k0 += 16) {
        float2 xv = *(const float2*)&g_X[(size_t)(row0 + xr) * EMB + k0 + xk];
        sX[xk][xr] = xv.x; sX[xk+1][xr] = xv.y;
        float4 cv = *(const float4*)&C[cr * EMB + k0 + ck];
        sC[ck+0][cr] = cv.x; sC[ck+1][cr] = cv.y; sC[ck+2][cr] = cv.z; sC[ck+3][cr] = cv.w;
        __syncthreads();
        #pragma unroll
        for (int kk = 0; kk < 16; kk++) {
            float2 x2 = *(const float2*)&sX[kk][ty << 1];
            float4 c4 = *(const float4*)&sC[kk][tx << 2];
            float cr4[4] = {c4.x, c4.y, c4.z, c4.w};
            #pragma unroll
            for (int j = 0; j < 4; j++) {
                acc[0][j] = fmaf(x2.x, cr4[j], acc[0][j]);
                acc[1][j] = fmaf(x2.y, cr4[j], acc[1][j]);
            }
        }
        __syncthreads();
    }
    float av[2][4];
    #pragma unroll
    for (int i = 0; i < 2; i++) {
        int row = row0 + (ty << 1) + i;
        float xs = g_xsq[row];
        float lgt[4];
        float mx = -1e30f;
        #pragma unroll
        for (int j = 0; j < 4; j++) {
            float d2 = xs + g_csq[(tx << 2) + j] - 2.f * acc[i][j];
            float dd = sqrtf(fmaxf(d2, 0.f));
            lgt[j] = -2.f * dd;
            mx = fmaxf(mx, lgt[j]);
        }
        #pragma unroll
        for (int off = 8; off; off >>= 1)
            mx = fmaxf(mx, __shfl_xor_sync(0xffffffffu, mx, off));
        float ps = 0.f;
        #pragma unroll
        for (int j = 0; j < 4; j++) { av[i][j] = expf(lgt[j] - mx); ps += av[i][j]; }
        #pragma unroll
        for (int off = 8; off; off >>= 1)
            ps += __shfl_xor_sync(0xffffffffu, ps, off);
        float4 ov;
        ov.x = av[i][0] / ps; ov.y = av[i][1] / ps;
        ov.z = av[i][2] / ps; ov.w = av[i][3] / ps;
        av[i][0] = ov.x; av[i][1] = ov.y; av[i][2] = ov.z; av[i][3] = ov.w;
        *(float4*)&a_out[(size_t)row * KCL + (tx << 2)] = ov;
    }
    #pragma unroll
    for (int j = 0; j < 4; j++)
        s_part[(tx << 2) + j][ty] = av[0][j] + av[1][j];
    __syncthreads();
    if (t < 64) {
        float s = 0.f;
        #pragma unroll
        for (int w = 0; w < 16; w++) s += s_part[t][w];
        g_asum_part[blockIdx.x * 64 + t] = s;
    }
}

// ---------------- DKM: split-K partials of a^T @ X -> g_Cpart ----------------
__global__ void __launch_bounds__(256) update_k(const float* __restrict__ a)
{
    if (g_done) return;
    __shared__ float sa[16][68];
    __shared__ float sx[16][68];
    int t = threadIdx.x, ty = t >> 4, tx = t & 15;
    int eb = blockIdx.x;  // 0..11
    int cb = blockIdx.y;  // 0..31
    int n0 = cb * 128;
    float acc[4][4] = {};
    int nn = t >> 4, c4 = (t & 15) << 2;
    for (int nt = 0; nt < 128; nt += 16) {
        int n = n0 + nt + nn;
        *(float4*)&sa[nn][c4] = *(const float4*)&a[(size_t)n * KCL + c4];
        *(float4*)&sx[nn][c4] = *(const float4*)&g_X[(size_t)n * EMB + eb * 64 + c4];
        __syncthreads();
        #pragma unroll
        for (int q = 0; q < 16; q++) {
            float4 a4 = *(const float4*)&sa[q][ty << 2];
            float4 x4 = *(const float4*)&sx[q][tx << 2];
            float ar[4] = {a4.x, a4.y, a4.z, a4.w};
            float xr4[4] = {x4.x, x4.y, x4.z, x4.w};
            #pragma unroll
            for (int i = 0; i < 4; i++)
                #pragma unroll
                for (int j = 0; j < 4; j++)
                    acc[i][j] = fmaf(ar[i], xr4[j], acc[i][j]);
        }
        __syncthreads();
    }
    #pragma unroll
    for (int i = 0; i < 4; i++)
        #pragma unroll
        for (int j = 0; j < 4; j++)
            g_Cpart[(size_t)(cb * 64 + (ty << 2) + i) * EMB + eb * 64 + (tx << 2) + j] = acc[i][j];
}

// ---------------- DKM: reduce partials -> Cnew = (a^T X)/a_sum; diff partials -------
__global__ void __launch_bounds__(1024) finalize_k(const float* __restrict__ C)
{
    if (g_done) return;
    __shared__ float s_asum[64];
    __shared__ float red[32];
    int t = threadIdx.x;
    if (t < 64) {
        float s = 0.f;
        #pragma unroll 4
        for (int bb = 0; bb < 128; bb++) s += g_asum_part[bb * 64 + t];
        s_asum[t] = s + DKMEPS;
    }
    __syncthreads();
    int i = blockIdx.x * 1024 + t;
    float s = 0.f;
    #pragma unroll
    for (int p = 0; p < 32; p++) s += g_Cpart[(size_t)p * (KCL * EMB) + i];
    float c = s / s_asum[i / EMB];
    g_Cnew[i] = c;
    float d = fabsf(c - C[i]);
    #pragma unroll
    for (int o = 16; o; o >>= 1) d += __shfl_xor_sync(0xffffffffu, d, o);
    if ((t & 31) == 0) red[t >> 5] = d;
    __syncthreads();
    if (t == 0) {
        float tot = 0.f;
        #pragma unroll
        for (int w = 0; w < 32; w++) tot += red[w];
        g_diff_part[blockIdx.x] = tot;
    }
}

// ---------------- host ----------------
extern "C" void kernel_launch(void* const* d_in, const int* in_sizes, int n_in,
                              void* d_out, int out_size)
{
    const float* x0     = (const float*)d_in[0];
    const float* fc1_w  = (const float*)d_in[1];
    const float* fc1_b  = (const float*)d_in[2];
    const float* fc2_w  = (const float*)d_in[3];
    const float* fc2_b  = (const float*)d_in[4];
    const float* inp_w  = (const float*)d_in[5];
    const float* inp_b  = (const float*)d_in[6];
    const float* out_w  = (const float*)d_in[7];
    const float* out_b  = (const float*)d_in[8];
    const float* ln_g   = (const float*)d_in[9];
    const float* ln_b   = (const float*)d_in[10];
    const int*   iidx   = (const int*)d_in[11];

    float* outC = (float*)d_out;              // [64, 768]
    float* outA = (float*)d_out + KCL * EMB;  // [4096, 64]

    void *pA, *pQ, *pB;
    cudaGetSymbolAddress(&pA, g_bufA);
    cudaGetSymbolAddress(&pQ, g_QKV);
    cudaGetSymbolAddress(&pB, g_bufB);
    float* bufA = (float*)pA;
    float* qkv  = (float*)pQ;
    float* bufB = (float*)pB;

    cudaFuncSetAttribute(flash2, cudaFuncAttributeMaxDynamicSharedMemorySize, FL_SMEM);

    // ---- transform ----
    sgemm128<true ><<<dim3(EMB/128,  NPTS/128), 256>>>(x0,   fc1_w, fc1_b, bufA, EMB,  EMB);
    sgemm128<false><<<dim3(QKVW/128, NPTS/128), 256>>>(bufA, inp_w, inp_b, qkv,  QKVW, EMB);
    flash2<<<dim3(32, 12), 256, FL_SMEM>>>(qkv, bufB);
    sgemm128<false><<<dim3(EMB/128, NPTS/128), 256>>>(bufB, out_w, out_b, bufA, EMB, EMB);
    sgemm128<true ><<<dim3(EMB/128, NPTS/128), 256>>>(bufA, fc2_w, fc2_b, bufB, EMB, EMB);
    ln_kernel<<<NPTS, 256>>>(x0, bufB, ln_g, ln_b);

    // ---- DKM loop: initial step (it=0) + up to 100 bodies, freeze-flag semantics ----
    gather_init<<<KCL, 768>>>(iidx, outC);
    for (int it = 0; it <= 100; it++) {
        if (it > 0) advance_k<<<KCL, 768>>>(outC);
        assign_k<<<NPTS/32, 256>>>(outC, outA);
        if (it < 100) {
            update_k<<<dim3(12, 32), 256>>>(outA);
            finalize_k<<<48, 1024>>>(outC);
        }
    }
}

// round 3
// speedup vs baseline: 1.1320x; 1.1152x over previous
#include <cuda_runtime.h>

#define NPTS   4096
#define EMB    768
#define QKVW   2304
#define KCL    64
#define THRESH 1e-4f
#define DKMEPS 1e-6f
#define LNEPS  1e-5f
#define NB     148      // persistent grid size (<= SM count, 1 CTA/SM guaranteed)

// ---------------- scratch (static device globals; no allocation) ----------------
__device__ float g_bufA[NPTS * EMB];
__device__ float g_QKV [NPTS * QKVW];
__device__ float g_bufB[NPTS * EMB];
__device__ float g_X   [NPTS * EMB];
__device__ float g_xsq [NPTS];
__device__ float g_Cprev[KCL * EMB];
__device__ float g_Cpart[32 * KCL * EMB];     // split-N partials of a^T X
__device__ float g_asum_part[128 * KCL];      // per-assign-tile partials of sum_n a[n,k]
__device__ float g_csqp[192];                 // per-chunk partials of |c_k|^2
__device__ float g_diffp[192];                // per-chunk partials of sum|dC|
__device__ unsigned g_bar_gen;
__device__ unsigned g_bar_cnt;

// ---------------- helpers ----------------
template<int NW>
__device__ __forceinline__ float blockSum(float v, float* red) {
    #pragma unroll
    for (int o = 16; o; o >>= 1) v += __shfl_xor_sync(0xffffffffu, v, o);
    int t = threadIdx.x;
    if ((t & 31) == 0) red[t >> 5] = v;
    __syncthreads();
    float s = 0.f;
    #pragma unroll
    for (int w = 0; w < NW; w++) s += red[w];
    __syncthreads();
    return s;
}

// sense-reversing grid barrier; safe because grid == NB and all CTAs resident
__device__ __forceinline__ void gridbar() {
    __syncthreads();
    if (threadIdx.x == 0) {
        unsigned gen = *(volatile unsigned*)&g_bar_gen;
        __threadfence();
        if (atomicAdd(&g_bar_cnt, 1u) == NB - 1) {
            g_bar_cnt = 0;
            __threadfence();
            *(volatile unsigned*)&g_bar_gen = gen + 1;
        } else {
            while (*(volatile unsigned*)&g_bar_gen == gen) { __nanosleep(32); }
        }
        __threadfence();
    }
    __syncthreads();
}

// ---------------- SGEMM 128x64: OUT[M,N] = act(A[M,K] @ W[N,K]^T + bias) ----------
// grid (Nn/64, M/128), 256 threads, double-buffered, 8x4 per thread
template<bool RELU>
__global__ void __launch_bounds__(256) sgemm_12864(
    const float* __restrict__ A, const float* __restrict__ W,
    const float* __restrict__ bias, float* __restrict__ OUT,
    int Nn, int Kd)
{
    __shared__ float sA[2][8][132];
    __shared__ float sB[2][8][68];
    const int t  = threadIdx.x;
    const int tx = t & 15, ty = t >> 4;
    const int row0 = blockIdx.y * 128, col0 = blockIdx.x * 64;
    const int lrA = t >> 1, lkA = (t & 1) << 2;   // float4 A loads
    const int lrB = t >> 2, lkB = (t & 3) << 1;   // float2 B loads
    const float* Ap = A + (size_t)(row0 + lrA) * Kd + lkA;
    const float* Wp = W + (size_t)(col0 + lrB) * Kd + lkB;

    float acc[8][4] = {};

    {
        float4 av = *(const float4*)(Ap);
        float2 bv = *(const float2*)(Wp);
        sA[0][lkA+0][lrA] = av.x; sA[0][lkA+1][lrA] = av.y;
        sA[0][lkA+2][lrA] = av.z; sA[0][lkA+3][lrA] = av.w;
        sB[0][lkB+0][lrB] = bv.x; sB[0][lkB+1][lrB] = bv.y;
    }
    __syncthreads();

    const int nk = Kd >> 3;
    for (int ks = 0; ks < nk; ks++) {
        const int cur = ks & 1;
        float4 a2; float2 b2;
        const bool more = (ks + 1 < nk);
        if (more) {
            a2 = *(const float4*)(Ap + (ks + 1) * 8);
            b2 = *(const float2*)(Wp + (ks + 1) * 8);
        }
        #pragma unroll
        for (int kk = 0; kk < 8; kk++) {
            float4 a0 = *(const float4*)&sA[cur][kk][ty << 3];
            float4 a1 = *(const float4*)&sA[cur][kk][(ty << 3) + 4];
            float4 b4 = *(const float4*)&sB[cur][kk][tx << 2];
            float ar[8] = {a0.x,a0.y,a0.z,a0.w,a1.x,a1.y,a1.z,a1.w};
            float br[4] = {b4.x,b4.y,b4.z,b4.w};
            #pragma unroll
            for (int i = 0; i < 8; i++)
                #pragma unroll
                for (int j = 0; j < 4; j++)
                    acc[i][j] = fmaf(ar[i], br[j], acc[i][j]);
        }
        if (more) {
            const int nxt = cur ^ 1;
            sA[nxt][lkA+0][lrA] = a2.x; sA[nxt][lkA+1][lrA] = a2.y;
            sA[nxt][lkA+2][lrA] = a2.z; sA[nxt][lkA+3][lrA] = a2.w;
            sB[nxt][lkB+0][lrB] = b2.x; sB[nxt][lkB+1][lrB] = b2.y;
            __syncthreads();
        }
    }
    #pragma unroll
    for (int i = 0; i < 8; i++) {
        float4 ov;
        float* r = &ov.x;
        #pragma unroll
        for (int j = 0; j < 4; j++) {
            float v = acc[i][j] + bias[col0 + (tx << 2) + j];
            if (RELU) v = fmaxf(v, 0.f);
            r[j] = v;
        }
        *(float4*)&OUT[(size_t)(row0 + (ty << 3) + i) * Nn + col0 + (tx << 2)] = ov;
    }
}

// ---------------- flash attention v2: Q-tile 128, K-tile 64, hd=64 ----------------
#define FL_SMEM ((64*132 + 64*68 + 64*68 + 64*132) * 4)
__global__ void __launch_bounds__(256) flash2(
    const float* __restrict__ QKV, float* __restrict__ O)
{
    extern __shared__ float sm[];
    float* sQ = sm;
    float* sK = sQ + 64 * 132;
    float* sV = sK + 64 * 68;
    float* sP = sV + 64 * 68;
    const int t  = threadIdx.x;
    const int tx = t & 15, ty = t >> 4;
    const int qb = blockIdx.x, h = blockIdx.y;

    {
        int qr = t & 127;
        int half = t >> 7;
        #pragma unroll
        for (int p = 0; p < 8; p++) {
            int d4 = half * 32 + p * 4;
            float4 q = *(const float4*)&QKV[(size_t)(qb * 128 + qr) * QKVW + h * 64 + d4];
            sQ[(d4+0)*132 + qr] = q.x; sQ[(d4+1)*132 + qr] = q.y;
            sQ[(d4+2)*132 + qr] = q.z; sQ[(d4+3)*132 + qr] = q.w;
        }
    }
    float o[8][4] = {};
    float m[8], l[8];
    #pragma unroll
    for (int i = 0; i < 8; i++) { m[i] = -1e30f; l[i] = 0.f; }

    for (int kb = 0; kb < 64; kb++) {
        {
            int kr = t & 63;
            int half = t >> 6;
            #pragma unroll
            for (int p = 0; p < 4; p++) {
                int d4 = half * 16 + p * 4;
                float4 kv = *(const float4*)&QKV[(size_t)(kb * 64 + kr) * QKVW + 768 + h * 64 + d4];
                sK[(d4+0)*68 + kr] = kv.x; sK[(d4+1)*68 + kr] = kv.y;
                sK[(d4+2)*68 + kr] = kv.z; sK[(d4+3)*68 + kr] = kv.w;
                float4 vv = *(const float4*)&QKV[(size_t)(kb * 64 + kr) * QKVW + 1536 + h * 64 + d4];
                *(float4*)&sV[kr*68 + d4] = vv;
            }
        }
        __syncthreads();
        float s[8][4] = {};
        #pragma unroll
        for (int d = 0; d < 64; d++) {
            float4 a0 = *(const float4*)&sQ[d*132 + (ty << 3)];
            float4 a1 = *(const float4*)&sQ[d*132 + (ty << 3) + 4];
            float4 b4 = *(const float4*)&sK[d*68 + (tx << 2)];
            float ar[8] = {a0.x,a0.y,a0.z,a0.w,a1.x,a1.y,a1.z,a1.w};
            float br[4] = {b4.x,b4.y,b4.z,b4.w};
            #pragma unroll
            for (int i = 0; i < 8; i++)
                #pragma unroll
                for (int j = 0; j < 4; j++)
                    s[i][j] = fmaf(ar[i], br[j], s[i][j]);
        }
        float p[8][4];
        #pragma unroll
        for (int i = 0; i < 8; i++) {
            float mx = -1e30f;
            #pragma unroll
            for (int j = 0; j < 4; j++) { s[i][j] *= 0.125f; mx = fmaxf(mx, s[i][j]); }
            #pragma unroll
            for (int off = 8; off; off >>= 1)
                mx = fmaxf(mx, __shfl_xor_sync(0xffffffffu, mx, off));
            float mn = fmaxf(m[i], mx);
            float sc = expf(m[i] - mn);
            float ps = 0.f;
            #pragma unroll
            for (int j = 0; j < 4; j++) { p[i][j] = expf(s[i][j] - mn); ps += p[i][j]; }
            #pragma unroll
            for (int off = 8; off; off >>= 1)
                ps += __shfl_xor_sync(0xffffffffu, ps, off);
            l[i] = l[i] * sc + ps;
            m[i] = mn;
            #pragma unroll
            for (int j = 0; j < 4; j++) o[i][j] *= sc;
        }
        #pragma unroll
        for (int i = 0; i < 8; i++)
            #pragma unroll
            for (int j = 0; j < 4; j++)
                sP[((tx << 2) + j) * 132 + (ty << 3) + i] = p[i][j];
        __syncthreads();
        #pragma unroll
        for (int c = 0; c < 64; c++) {
            float4 p0 = *(const float4*)&sP[c*132 + (ty << 3)];
            float4 p1 = *(const float4*)&sP[c*132 + (ty << 3) + 4];
            float4 v4 = *(const float4*)&sV[c*68 + (tx << 2)];
            float pa[8] = {p0.x,p0.y,p0.z,p0.w,p1.x,p1.y,p1.z,p1.w};
            float vb[4] = {v4.x,v4.y,v4.z,v4.w};
            #pragma unroll
            for (int i = 0; i < 8; i++)
                #pragma unroll
                for (int j = 0; j < 4; j++)
                    o[i][j] = fmaf(pa[i], vb[j], o[i][j]);
        }
        __syncthreads();
    }
    #pragma unroll
    for (int i = 0; i < 8; i++) {
        float inv = 1.f / l[i];
        float4 ov;
        ov.x = o[i][0]*inv; ov.y = o[i][1]*inv; ov.z = o[i][2]*inv; ov.w = o[i][3]*inv;
        *(float4*)&O[(size_t)(qb * 128 + (ty << 3) + i) * EMB + h * 64 + (tx << 2)] = ov;
    }
}

// ---------------- residual + layernorm + xsq ----------------
__global__ void __launch_bounds__(256) ln_kernel(
    const float* __restrict__ x0, const float* __restrict__ y,
    const float* __restrict__ lg, const float* __restrict__ lb)
{
    __shared__ float red[8];
    int r = blockIdx.x, t = threadIdx.x;
    float z[3];
    float s = 0.f;
    #pragma unroll
    for (int i = 0; i < 3; i++) {
        int c = t + i * 256;
        z[i] = 0.5f * x0[(size_t)r * EMB + c] + 0.5f * y[(size_t)r * EMB + c];
        s += z[i];
    }
    s = blockSum<8>(s, red);
    float mu = s * (1.f / 768.f);
    float v = 0.f;
    #pragma unroll
    for (int i = 0; i < 3; i++) { float dz = z[i] - mu; v = fmaf(dz, dz, v); }
    v = blockSum<8>(v, red);
    float rstd = rsqrtf(v * (1.f / 768.f) + LNEPS);
    float q = 0.f;
    #pragma unroll
    for (int i = 0; i < 3; i++) {
        int c = t + i * 256;
        float xv = (z[i] - mu) * rstd * lg[c] + lb[c];
        g_X[(size_t)r * EMB + c] = xv;
        q = fmaf(xv, xv, q);
    }
    q = blockSum<8>(q, red);
    if (t == 0) g_xsq[r] = q;
}

// ================= persistent DKM: whole loop in ONE kernel ======================
// grid = NB blocks x 256 threads; device-side convergence break.
__global__ void __launch_bounds__(256) dkm_persist(
    const int* __restrict__ idx, float* __restrict__ outC, float* __restrict__ outA)
{
    // phase-A smem
    __shared__ float sX[16][36];
    __shared__ float sC[16][68];
    __shared__ float s_part[64][17];
    __shared__ float s_csq[64];
    // phase-B smem
    __shared__ float sa[16][68];
    __shared__ float sx[16][68];
    // shared reductions / broadcast
    __shared__ float red[8];
    __shared__ float sbc;

    const int b = blockIdx.x;
    const int t = threadIdx.x;
    const int ty = t >> 4, tx = t & 15;

    // ---- init: gather C0 = X[idx], csq chunk partials ----
    for (int c = b; c < 192; c += NB) {
        int k = c / 3;
        int i = c * 256 + t;
        int e = i - k * EMB;
        float v = g_X[(size_t)idx[k] * EMB + e];
        outC[i] = v;
        float s = blockSum<8>(v * v, red);
        if (t == 0) g_csqp[c] = s;
    }
    gridbar();

    for (int it = 0; it <= 100; it++) {
        // ---- break check (identical decision in every block) ----
        if (it > 0) {
            if (t == 0) {
                float d = 0.f;
                for (int c = 0; c < 192; c++) d += g_diffp[c];
                sbc = d;
            }
            __syncthreads();
            if (sbc <= THRESH) {
                // restore outC to C_{it-1} (stashed in g_Cprev) and exit
                for (int c = b; c < 192; c += NB)
                    outC[c * 256 + t] = g_Cprev[c * 256 + t];
                return;
            }
        }

        // ---- phase A: assignments a = softmax(-2*cdist(X,C)) ----
        if (b < 128) {
            // csq per cluster from chunk partials
            if (t < 64) s_csq[t] = g_csqp[3*t] + g_csqp[3*t+1] + g_csqp[3*t+2];
            __syncthreads();
            const int row0 = b * 32;
            float acc[2][4] = {};
            const int xr = t >> 3, xk = (t & 7) << 1;
            const int cr = t >> 2, ck = (t & 3) << 2;
            for (int k0 = 0; k0 < EMB; k0 += 16) {
                float2 xv = *(const float2*)&g_X[(size_t)(row0 + xr) * EMB + k0 + xk];
                sX[xk][xr] = xv.x; sX[xk+1][xr] = xv.y;
                float4 cv = *(const float4*)&outC[cr * EMB + k0 + ck];
                sC[ck+0][cr] = cv.x; sC[ck+1][cr] = cv.y;
                sC[ck+2][cr] = cv.z; sC[ck+3][cr] = cv.w;
                __syncthreads();
                #pragma unroll
                for (int kk = 0; kk < 16; kk++) {
                    float2 x2 = *(const float2*)&sX[kk][ty << 1];
                    float4 c4 = *(const float4*)&sC[kk][tx << 2];
                    float cr4[4] = {c4.x, c4.y, c4.z, c4.w};
                    #pragma unroll
                    for (int j = 0; j < 4; j++) {
                        acc[0][j] = fmaf(x2.x, cr4[j], acc[0][j]);
                        acc[1][j] = fmaf(x2.y, cr4[j], acc[1][j]);
                    }
                }
                __syncthreads();
            }
            float av[2][4];
            #pragma unroll
            for (int i = 0; i < 2; i++) {
                int row = row0 + (ty << 1) + i;
                float xs = g_xsq[row];
                float lgt[4];
                float mx = -1e30f;
                #pragma unroll
                for (int j = 0; j < 4; j++) {
                    float d2 = xs + s_csq[(tx << 2) + j] - 2.f * acc[i][j];
                    float dd = sqrtf(fmaxf(d2, 0.f));
                    lgt[j] = -2.f * dd;
                    mx = fmaxf(mx, lgt[j]);
                }
                #pragma unroll
                for (int off = 8; off; off >>= 1)
                    mx = fmaxf(mx, __shfl_xor_sync(0xffffffffu, mx, off));
                float ps = 0.f;
                #pragma unroll
                for (int j = 0; j < 4; j++) { av[i][j] = expf(lgt[j] - mx); ps += av[i][j]; }
                #pragma unroll
                for (int off = 8; off; off >>= 1)
                    ps += __shfl_xor_sync(0xffffffffu, ps, off);
                float4 ov;
                ov.x = av[i][0] / ps; ov.y = av[i][1] / ps;
                ov.z = av[i][2] / ps; ov.w = av[i][3] / ps;
                av[i][0] = ov.x; av[i][1] = ov.y; av[i][2] = ov.z; av[i][3] = ov.w;
                *(float4*)&outA[(size_t)row * KCL + (tx << 2)] = ov;
            }
            #pragma unroll
            for (int j = 0; j < 4; j++)
                s_part[(tx << 2) + j][ty] = av[0][j] + av[1][j];
            __syncthreads();
            if (t < 64) {
                float s = 0.f;
                #pragma unroll
                for (int w = 0; w < 16; w++) s += s_part[t][w];
                g_asum_part[b * 64 + t] = s;
            }
        }
        if (it == 100) break;   // a_100 written; outC already = C_100; done
        gridbar();

        // ---- phase B: split-N partials of a^T X -> g_Cpart ----
        for (int tt = b; tt < 384; tt += NB) {
            const int eb = tt % 12;
            const int cb = tt / 12;
            const int n0 = cb * 128;
            float acc[4][4] = {};
            const int nn = t >> 4, c4 = (t & 15) << 2;
            for (int nt = 0; nt < 128; nt += 16) {
                int n = n0 + nt + nn;
                *(float4*)&sa[nn][c4] = *(const float4*)&outA[(size_t)n * KCL + c4];
                *(float4*)&sx[nn][c4] = *(const float4*)&g_X[(size_t)n * EMB + eb * 64 + c4];
                __syncthreads();
                #pragma unroll
                for (int q = 0; q < 16; q++) {
                    float4 a4 = *(const float4*)&sa[q][ty << 2];
                    float4 x4 = *(const float4*)&sx[q][tx << 2];
                    float ar[4] = {a4.x, a4.y, a4.z, a4.w};
                    float xr4[4] = {x4.x, x4.y, x4.z, x4.w};
                    #pragma unroll
                    for (int i = 0; i < 4; i++)
                        #pragma unroll
                        for (int j = 0; j < 4; j++)
                            acc[i][j] = fmaf(ar[i], xr4[j], acc[i][j]);
                }
                __syncthreads();
            }
            #pragma unroll
            for (int i = 0; i < 4; i++)
                #pragma unroll
                for (int j = 0; j < 4; j++)
                    g_Cpart[(size_t)cb * (KCL*EMB) + (size_t)((ty << 2) + i) * EMB + eb * 64 + (tx << 2) + j] = acc[i][j];
        }
        gridbar();

        // ---- phase C: finalize Cnew, stash old C, diff & csq partials ----
        for (int c = b; c < 192; c += NB) {
            const int k = c / 3;
            const int i = c * 256 + t;
            // a_sum over 128 assign-tile partials (deterministic tree order)
            float part = (t < 128) ? g_asum_part[t * 64 + k] : 0.f;
            float asum = blockSum<8>(part, red) + DKMEPS;
            float s = 0.f;
            #pragma unroll
            for (int p = 0; p < 32; p++) s += g_Cpart[(size_t)p * (KCL*EMB) + i];
            float cn = s / asum;
            float old = outC[i];
            g_Cprev[i] = old;
            outC[i] = cn;
            float d = blockSum<8>(fabsf(cn - old), red);
            float q = blockSum<8>(cn * cn, red);
            if (t == 0) { g_diffp[c] = d; g_csqp[c] = q; }
        }
        gridbar();
    }
}

// ---------------- host ----------------
extern "C" void kernel_launch(void* const* d_in, const int* in_sizes, int n_in,
                              void* d_out, int out_size)
{
    const float* x0     = (const float*)d_in[0];
    const float* fc1_w  = (const float*)d_in[1];
    const float* fc1_b  = (const float*)d_in[2];
    const float* fc2_w  = (const float*)d_in[3];
    const float* fc2_b  = (const float*)d_in[4];
    const float* inp_w  = (const float*)d_in[5];
    const float* inp_b  = (const float*)d_in[6];
    const float* out_w  = (const float*)d_in[7];
    const float* out_b  = (const float*)d_in[8];
    const float* ln_g   = (const float*)d_in[9];
    const float* ln_b   = (const float*)d_in[10];
    const int*   iidx   = (const int*)d_in[11];

    float* outC = (float*)d_out;              // [64, 768]
    float* outA = (float*)d_out + KCL * EMB;  // [4096, 64]

    void *pA, *pQ, *pB;
    cudaGetSymbolAddress(&pA, g_bufA);
    cudaGetSymbolAddress(&pQ, g_QKV);
    cudaGetSymbolAddress(&pB, g_bufB);
    float* bufA = (float*)pA;
    float* qkv  = (float*)pQ;
    float* bufB = (float*)pB;

    cudaFuncSetAttribute(flash2, cudaFuncAttributeMaxDynamicSharedMemorySize, FL_SMEM);

    // ---- transform ----
    sgemm_12864<true ><<<dim3(EMB/64,  NPTS/128), 256>>>(x0,   fc1_w, fc1_b, bufA, EMB,  EMB);
    sgemm_12864<false><<<dim3(QKVW/64, NPTS/128), 256>>>(bufA, inp_w, inp_b, qkv,  QKVW, EMB);
    flash2<<<dim3(32, 12), 256, FL_SMEM>>>(qkv, bufB);
    sgemm_12864<false><<<dim3(EMB/64, NPTS/128), 256>>>(bufB, out_w, out_b, bufA, EMB, EMB);
    sgemm_12864<true ><<<dim3(EMB/64, NPTS/128), 256>>>(bufA, fc2_w, fc2_b, bufB, EMB, EMB);
    ln_kernel<<<NPTS, 256>>>(x0, bufB, ln_g, ln_b);

    // ---- DKM: entire loop in one persistent kernel ----
    dkm_persist<<<NB, 256>>>(iidx, outC, outA);
}